// round 1
// baseline (speedup 1.0000x reference)
#include <cuda_runtime.h>
#include <math.h>

#define K  32
#define B  16384
#define DA 128

// scratch: softmax weights w[k, b]  (2 MB, __device__ global per allocation rules)
__device__ float g_w[K * B];

// ---------------------------------------------------------------------------
// Kernel 1: column softmax over K=32.  One thread per b. Fully coalesced
// (stride-B rows -> consecutive threads hit consecutive addresses).
// ---------------------------------------------------------------------------
__global__ void __launch_bounds__(256) softmax_kernel(const float* __restrict__ ne) {
    int b = blockIdx.x * blockDim.x + threadIdx.x;
    if (b >= B) return;

    float v[K];
    float m = -1e30f;
#pragma unroll
    for (int k = 0; k < K; k++) {
        v[k] = ne[k * B + b];
        m = fmaxf(m, v[k]);
    }
    float s = 0.0f;
#pragma unroll
    for (int k = 0; k < K; k++) {
        v[k] = expf(v[k] - m);
        s += v[k];
    }
    float inv = 1.0f / s;
#pragma unroll
    for (int k = 0; k < K; k++) {
        g_w[k * B + b] = v[k] * inv;
    }
}

// ---------------------------------------------------------------------------
// Kernel 2: one warp per b-row. Lane owns 4 contiguous d's (float4).
//   x_sum[b,d] = sum_k nt[k, b, d] * w[k, (b&127)*128 + d]   (reshape-trick index)
// Then scale by n_param, warp-dot with ew -> sigmoid -> effect,
// write effect to out[0:B) and effect*(tw*x_+tb) to out[B + b*128 + d].
// ---------------------------------------------------------------------------
__global__ void __launch_bounds__(256) fused_kernel(
    const float* __restrict__ nt,   // [K, B, DA]
    const float* __restrict__ np,   // [DA]
    const float* __restrict__ ew,   // [DA]
    const float* __restrict__ eb,   // [1]
    const float* __restrict__ tw,   // [DA]
    const float* __restrict__ tb,   // [DA]
    float* __restrict__ out)        // [B + B*DA]
{
    const int warp = (blockIdx.x * blockDim.x + threadIdx.x) >> 5;
    const int lane = threadIdx.x & 31;
    if (warp >= B) return;
    const int b = warp;

    // weight row segment used by this b (reshape trick): columns (b&127)*128 .. +127
    const int wbase = (b & 127) << 7;

    const float4* nt4 = reinterpret_cast<const float4*>(nt + (size_t)b * DA) + lane;
    // stride between k-slices, in float4 units: B*DA/4
    const size_t kstride4 = (size_t)B * DA / 4;

    float4 acc = make_float4(0.f, 0.f, 0.f, 0.f);

#pragma unroll 8
    for (int k = 0; k < K; k++) {
        float4 a = __ldg(nt4 + (size_t)k * kstride4);
        float4 w = __ldg(reinterpret_cast<const float4*>(g_w + k * B + wbase) + lane);
        acc.x = fmaf(a.x, w.x, acc.x);
        acc.y = fmaf(a.y, w.y, acc.y);
        acc.z = fmaf(a.z, w.z, acc.z);
        acc.w = fmaf(a.w, w.w, acc.w);
    }

    // x_ = n_param * x_sum
    const float4 npv = __ldg(reinterpret_cast<const float4*>(np) + lane);
    float4 x_;
    x_.x = npv.x * acc.x;
    x_.y = npv.y * acc.y;
    x_.z = npv.z * acc.z;
    x_.w = npv.w * acc.w;

    // effect = sigmoid(x_ . ew + eb)
    const float4 ewv = __ldg(reinterpret_cast<const float4*>(ew) + lane);
    float dot = x_.x * ewv.x + x_.y * ewv.y + x_.z * ewv.z + x_.w * ewv.w;
#pragma unroll
    for (int off = 16; off > 0; off >>= 1)
        dot += __shfl_xor_sync(0xFFFFFFFFu, dot, off);

    const float effect = 1.0f / (1.0f + expf(-(dot + __ldg(eb))));

    if (lane == 0) out[b] = effect;

    // effect * (tw * x_ + tb)
    const float4 twv = __ldg(reinterpret_cast<const float4*>(tw) + lane);
    const float4 tbv = __ldg(reinterpret_cast<const float4*>(tb) + lane);
    float4 r;
    r.x = effect * fmaf(twv.x, x_.x, tbv.x);
    r.y = effect * fmaf(twv.y, x_.y, tbv.y);
    r.z = effect * fmaf(twv.z, x_.z, tbv.z);
    r.w = effect * fmaf(twv.w, x_.w, tbv.w);

    reinterpret_cast<float4*>(out + B + (size_t)b * DA)[lane] = r;
}

// ---------------------------------------------------------------------------
// launch
// ---------------------------------------------------------------------------
extern "C" void kernel_launch(void* const* d_in, const int* in_sizes, int n_in,
                              void* d_out, int out_size) {
    // metadata order: x, neigh_effect, neigh_transform, n_param, ew, eb, tw, tb
    const float* ne = (const float*)d_in[1];
    const float* nt = (const float*)d_in[2];
    const float* np = (const float*)d_in[3];
    const float* ew = (const float*)d_in[4];
    const float* eb = (const float*)d_in[5];
    const float* tw = (const float*)d_in[6];
    const float* tb = (const float*)d_in[7];
    float* out = (float*)d_out;

    softmax_kernel<<<B / 256, 256>>>(ne);

    // one warp per b: B warps = B*32 threads; 256 threads/block -> 8 warps/block
    const int blocks = (B * 32) / 256;  // 2048
    fused_kernel<<<blocks, 256>>>(nt, np, ew, eb, tw, tb, out);
}

// round 2
// speedup vs baseline: 1.0892x; 1.0892x over previous
#include <cuda_runtime.h>
#include <math.h>

#define K  32
#define B  16384
#define DA 128
#define SPLITS 16   // CTAs per residue; each CTA handles 8 b-rows (one per warp)

// Single fused kernel.
//
// Index decode of the reference's reshape trick:
//   x_sum[b,d] = sum_k nt[k,b,d] * w[k, (b&127)*128 + d]
// so all b with the same residue r = b&127 use w columns [r*128, r*128+128).
// CTA (r, s) computes softmax for those 128 columns once into smem, then its
// 8 warps each stream one b-row: b = r + 128*(s*8 + warp).
__global__ void __launch_bounds__(256) fused_all(
    const float* __restrict__ ne,   // [K, B]
    const float* __restrict__ nt,   // [K, B, DA]
    const float* __restrict__ np,   // [DA]
    const float* __restrict__ ew,   // [DA]
    const float* __restrict__ eb,   // [1]
    const float* __restrict__ tw,   // [DA]
    const float* __restrict__ tb,   // [DA]
    float* __restrict__ out)        // [B + B*DA]
{
    const int r = blockIdx.x & 127;      // residue
    const int s = blockIdx.x >> 7;       // split in [0, SPLITS)
    const int t = threadIdx.x;

    __shared__ float wsm[K][DA];         // 16 KB softmax weights for this residue

    // ---- softmax prologue: threads 0..127 each own one column ----
    if (t < DA) {
        const int col = r * DA + t;
        float v[K];
        float m = -1e30f;
#pragma unroll
        for (int k = 0; k < K; k++) {
            v[k] = ne[k * B + col];
            m = fmaxf(m, v[k]);
        }
        float ssum = 0.0f;
#pragma unroll
        for (int k = 0; k < K; k++) {
            v[k] = expf(v[k] - m);
            ssum += v[k];
        }
        const float inv = 1.0f / ssum;
#pragma unroll
        for (int k = 0; k < K; k++) {
            wsm[k][t] = v[k] * inv;
        }
    }
    __syncthreads();

    // ---- main stream: one warp per b-row ----
    const int warp = t >> 5;
    const int lane = t & 31;
    const int b = r + 128 * (s * 8 + warp);

    const size_t kstride4 = (size_t)B * DA / 4;   // float4 stride between k-slices
    const float4* nt4 = reinterpret_cast<const float4*>(nt + (size_t)b * DA) + lane;
    const float4* w4  = reinterpret_cast<const float4*>(&wsm[0][0]) + lane;  // + k*32

    float4 acc = make_float4(0.f, 0.f, 0.f, 0.f);

    // Manually staged batches of 8 loads -> forces 8 LDG.128 in flight per thread.
#pragma unroll
    for (int k0 = 0; k0 < K; k0 += 8) {
        float4 a[8];
#pragma unroll
        for (int j = 0; j < 8; j++)
            a[j] = __ldg(nt4 + (size_t)(k0 + j) * kstride4);
#pragma unroll
        for (int j = 0; j < 8; j++) {
            const float4 w = w4[(k0 + j) * 32];   // conflict-free LDS.128
            acc.x = fmaf(a[j].x, w.x, acc.x);
            acc.y = fmaf(a[j].y, w.y, acc.y);
            acc.z = fmaf(a[j].z, w.z, acc.z);
            acc.w = fmaf(a[j].w, w.w, acc.w);
        }
    }

    // x_ = n_param * x_sum
    const float4 npv = __ldg(reinterpret_cast<const float4*>(np) + lane);
    float4 x_;
    x_.x = npv.x * acc.x;
    x_.y = npv.y * acc.y;
    x_.z = npv.z * acc.z;
    x_.w = npv.w * acc.w;

    // effect = sigmoid(x_ . ew + eb)
    const float4 ewv = __ldg(reinterpret_cast<const float4*>(ew) + lane);
    float dot = x_.x * ewv.x + x_.y * ewv.y + x_.z * ewv.z + x_.w * ewv.w;
#pragma unroll
    for (int off = 16; off > 0; off >>= 1)
        dot += __shfl_xor_sync(0xFFFFFFFFu, dot, off);

    const float effect = 1.0f / (1.0f + expf(-(dot + __ldg(eb))));

    if (lane == 0) out[b] = effect;

    // effect * (tw * x_ + tb)
    const float4 twv = __ldg(reinterpret_cast<const float4*>(tw) + lane);
    const float4 tbv = __ldg(reinterpret_cast<const float4*>(tb) + lane);
    float4 res;
    res.x = effect * fmaf(twv.x, x_.x, tbv.x);
    res.y = effect * fmaf(twv.y, x_.y, tbv.y);
    res.z = effect * fmaf(twv.z, x_.z, tbv.z);
    res.w = effect * fmaf(twv.w, x_.w, tbv.w);

    reinterpret_cast<float4*>(out + B + (size_t)b * DA)[lane] = res;
}

extern "C" void kernel_launch(void* const* d_in, const int* in_sizes, int n_in,
                              void* d_out, int out_size) {
    // metadata order: x, neigh_effect, neigh_transform, n_param, ew, eb, tw, tb
    const float* ne = (const float*)d_in[1];
    const float* nt = (const float*)d_in[2];
    const float* np = (const float*)d_in[3];
    const float* ew = (const float*)d_in[4];
    const float* eb = (const float*)d_in[5];
    const float* tw = (const float*)d_in[6];
    const float* tb = (const float*)d_in[7];
    float* out = (float*)d_out;

    // 128 residues x 16 splits = 2048 CTAs; 8 warps/CTA = 16384 warps = B rows
    fused_all<<<128 * SPLITS, 256>>>(ne, nt, np, ew, eb, tw, tb, out);
}

// round 3
// speedup vs baseline: 1.1671x; 1.0715x over previous
#include <cuda_runtime.h>
#include <math.h>

#define K  32
#define B  16384
#define DA 128
#define SPLITS 16   // CTAs per residue; each CTA handles 8 b-rows (one per warp)

// Single fused kernel.
//
// Index decode of the reference's reshape trick:
//   x_sum[b,d] = sum_k nt[k,b,d] * w[k, (b&127)*128 + d]
// so all b with the same residue r = b&127 use w columns [r*128, r*128+128).
// CTA (r, s) computes softmax for those 128 columns once into smem, then its
// 8 warps each stream one b-row: b = r + 128*(s*8 + warp).
//
// nt is a 256 MB single-use stream (2x the L2) -> __ldcs (evict-first) so it
// doesn't churn L2; outputs are write-once -> __stcs.

__device__ __forceinline__ float4 ldcs4(const float4* p) {
    return __ldcs(p);
}

__global__ void __launch_bounds__(256) fused_all(
    const float* __restrict__ ne,   // [K, B]
    const float* __restrict__ nt,   // [K, B, DA]
    const float* __restrict__ np,   // [DA]
    const float* __restrict__ ew,   // [DA]
    const float* __restrict__ eb,   // [1]
    const float* __restrict__ tw,   // [DA]
    const float* __restrict__ tb,   // [DA]
    float* __restrict__ out)        // [B + B*DA]
{
    const int r = blockIdx.x & 127;      // residue
    const int s = blockIdx.x >> 7;       // split in [0, SPLITS)
    const int t = threadIdx.x;

    __shared__ float wsm[K][DA];         // 16 KB softmax weights for this residue

    // ---- softmax prologue: threads 0..127 each own one column ----
    if (t < DA) {
        const int col = r * DA + t;
        float v[K];
        float m = -1e30f;
#pragma unroll
        for (int k = 0; k < K; k++) {
            v[k] = __ldg(ne + k * B + col);
            m = fmaxf(m, v[k]);
        }
        float ssum = 0.0f;
#pragma unroll
        for (int k = 0; k < K; k++) {
            v[k] = __expf(v[k] - m);
            ssum += v[k];
        }
        const float inv = __frcp_rn(ssum);
#pragma unroll
        for (int k = 0; k < K; k++) {
            wsm[k][t] = v[k] * inv;
        }
    }
    __syncthreads();

    // ---- main stream: one warp per b-row ----
    const int warp = t >> 5;
    const int lane = t & 31;
    const int b = r + 128 * (s * 8 + warp);

    const size_t kstride4 = (size_t)B * DA / 4;   // float4 stride between k-slices
    const float4* nt4 = reinterpret_cast<const float4*>(nt + (size_t)b * DA) + lane;
    const float4* w4  = reinterpret_cast<const float4*>(&wsm[0][0]) + lane;  // + k*32

    float4 acc = make_float4(0.f, 0.f, 0.f, 0.f);

    // Manually staged batches of 8 loads -> 8 LDG.128 in flight per thread.
#pragma unroll
    for (int k0 = 0; k0 < K; k0 += 8) {
        float4 a[8];
#pragma unroll
        for (int j = 0; j < 8; j++)
            a[j] = ldcs4(nt4 + (size_t)(k0 + j) * kstride4);   // streaming, evict-first
#pragma unroll
        for (int j = 0; j < 8; j++) {
            const float4 w = w4[(k0 + j) * 32];   // conflict-free LDS.128
            acc.x = fmaf(a[j].x, w.x, acc.x);
            acc.y = fmaf(a[j].y, w.y, acc.y);
            acc.z = fmaf(a[j].z, w.z, acc.z);
            acc.w = fmaf(a[j].w, w.w, acc.w);
        }
    }

    // x_ = n_param * x_sum
    const float4 npv = __ldg(reinterpret_cast<const float4*>(np) + lane);
    float4 x_;
    x_.x = npv.x * acc.x;
    x_.y = npv.y * acc.y;
    x_.z = npv.z * acc.z;
    x_.w = npv.w * acc.w;

    // effect = sigmoid(x_ . ew + eb)
    const float4 ewv = __ldg(reinterpret_cast<const float4*>(ew) + lane);
    float dot = x_.x * ewv.x + x_.y * ewv.y + x_.z * ewv.z + x_.w * ewv.w;
#pragma unroll
    for (int off = 16; off > 0; off >>= 1)
        dot += __shfl_xor_sync(0xFFFFFFFFu, dot, off);

    const float effect = __frcp_rn(1.0f + __expf(-(dot + __ldg(eb))));

    if (lane == 0) __stcs(out + b, effect);

    // effect * (tw * x_ + tb)
    const float4 twv = __ldg(reinterpret_cast<const float4*>(tw) + lane);
    const float4 tbv = __ldg(reinterpret_cast<const float4*>(tb) + lane);
    float4 res;
    res.x = effect * fmaf(twv.x, x_.x, tbv.x);
    res.y = effect * fmaf(twv.y, x_.y, tbv.y);
    res.z = effect * fmaf(twv.z, x_.z, tbv.z);
    res.w = effect * fmaf(twv.w, x_.w, tbv.w);

    __stcs(reinterpret_cast<float4*>(out + B + (size_t)b * DA) + lane, res);
}

extern "C" void kernel_launch(void* const* d_in, const int* in_sizes, int n_in,
                              void* d_out, int out_size) {
    // metadata order: x, neigh_effect, neigh_transform, n_param, ew, eb, tw, tb
    const float* ne = (const float*)d_in[1];
    const float* nt = (const float*)d_in[2];
    const float* np = (const float*)d_in[3];
    const float* ew = (const float*)d_in[4];
    const float* eb = (const float*)d_in[5];
    const float* tw = (const float*)d_in[6];
    const float* tb = (const float*)d_in[7];
    float* out = (float*)d_out;

    // 128 residues x 16 splits = 2048 CTAs; 8 warps/CTA = 16384 warps = B rows
    fused_all<<<128 * SPLITS, 256>>>(ne, nt, np, ew, eb, tw, tb, out);
}

// round 4
// speedup vs baseline: 1.1734x; 1.0054x over previous
#include <cuda_runtime.h>
#include <math.h>

#define K  32
#define B  16384
#define DA 128
#define GROUPS 4          // CTA groups per residue
#define ROWS_PER_WARP 4   // (B/128) / (GROUPS*8 warps) = 128/32 = 4

// Persistent single-wave fused kernel.
//
// Reshape-trick index: x_sum[b,d] = sum_k nt[k,b,d] * w[k, (b&127)*128 + d],
// so all b with residue r = b&127 share one 128-column softmax. CTA (r,g)
// computes it once into smem, then each of its 8 warps streams 4 b-rows.
//
// grid = 128*4 = 512 CTAs, 4 CTAs/SM (regs pinned <=64) -> one wave on 152 SMs:
// no wave-transition stalls, 4x fewer softmax prologues than round 3.
//
// nt (256 MB, single-use, 2x L2) -> __ldcs evict-first; outputs -> __stcs.

__global__ void __launch_bounds__(256, 4) fused_all(
    const float* __restrict__ ne,   // [K, B]
    const float* __restrict__ nt,   // [K, B, DA]
    const float* __restrict__ np,   // [DA]
    const float* __restrict__ ew,   // [DA]
    const float* __restrict__ eb,   // [1]
    const float* __restrict__ tw,   // [DA]
    const float* __restrict__ tb,   // [DA]
    float* __restrict__ out)        // [B + B*DA]
{
    const int r = blockIdx.x >> 2;       // residue 0..127
    const int g = blockIdx.x & 3;        // group   0..3
    const int t = threadIdx.x;

    __shared__ float wsm[K][DA];         // 16 KB softmax weights for this residue

    // ---- softmax prologue: threads 0..127 each own one column ----
    if (t < DA) {
        const int col = r * DA + t;
        float v[K];
        float m = -1e30f;
#pragma unroll
        for (int k = 0; k < K; k++) {
            v[k] = __ldg(ne + k * B + col);
            m = fmaxf(m, v[k]);
        }
        float ssum = 0.0f;
#pragma unroll
        for (int k = 0; k < K; k++) {
            v[k] = __expf(v[k] - m);
            ssum += v[k];
        }
        const float inv = __frcp_rn(ssum);
#pragma unroll
        for (int k = 0; k < K; k++) {
            wsm[k][t] = v[k] * inv;
        }
    }
    __syncthreads();

    const int warp = t >> 5;
    const int lane = t & 31;

    // hoisted per-lane epilogue constants (reused across the 4 rows)
    const float4 npv = __ldg(reinterpret_cast<const float4*>(np) + lane);
    const float4 ewv = __ldg(reinterpret_cast<const float4*>(ew) + lane);
    const float4 twv = __ldg(reinterpret_cast<const float4*>(tw) + lane);
    const float4 tbv = __ldg(reinterpret_cast<const float4*>(tb) + lane);
    const float  ebv = __ldg(eb);

    const size_t kstride4 = (size_t)B * DA / 4;   // float4 stride between k-slices
    const float4* w4 = reinterpret_cast<const float4*>(&wsm[0][0]) + lane;  // + k*32

    // ---- stream 4 b-rows per warp ----
#pragma unroll
    for (int i = 0; i < ROWS_PER_WARP; i++) {
        const int m = g * 32 + warp * ROWS_PER_WARP + i;   // 0..127
        const int b = r + 128 * m;

        const float4* nt4 = reinterpret_cast<const float4*>(nt + (size_t)b * DA) + lane;

        float4 acc = make_float4(0.f, 0.f, 0.f, 0.f);

        // staged batches of 8 -> 8 LDG.128 in flight per thread
#pragma unroll
        for (int k0 = 0; k0 < K; k0 += 8) {
            float4 a[8];
#pragma unroll
            for (int j = 0; j < 8; j++)
                a[j] = __ldcs(nt4 + (size_t)(k0 + j) * kstride4);
#pragma unroll
            for (int j = 0; j < 8; j++) {
                const float4 w = w4[(k0 + j) * 32];   // conflict-free LDS.128
                acc.x = fmaf(a[j].x, w.x, acc.x);
                acc.y = fmaf(a[j].y, w.y, acc.y);
                acc.z = fmaf(a[j].z, w.z, acc.z);
                acc.w = fmaf(a[j].w, w.w, acc.w);
            }
        }

        // x_ = n_param * x_sum
        float4 x_;
        x_.x = npv.x * acc.x;
        x_.y = npv.y * acc.y;
        x_.z = npv.z * acc.z;
        x_.w = npv.w * acc.w;

        // effect = sigmoid(x_ . ew + eb)
        float dot = x_.x * ewv.x + x_.y * ewv.y + x_.z * ewv.z + x_.w * ewv.w;
#pragma unroll
        for (int off = 16; off > 0; off >>= 1)
            dot += __shfl_xor_sync(0xFFFFFFFFu, dot, off);

        const float effect = __frcp_rn(1.0f + __expf(-(dot + ebv)));

        if (lane == 0) __stcs(out + b, effect);

        float4 res;
        res.x = effect * fmaf(twv.x, x_.x, tbv.x);
        res.y = effect * fmaf(twv.y, x_.y, tbv.y);
        res.z = effect * fmaf(twv.z, x_.z, tbv.z);
        res.w = effect * fmaf(twv.w, x_.w, tbv.w);

        __stcs(reinterpret_cast<float4*>(out + B + (size_t)b * DA) + lane, res);
    }
}

extern "C" void kernel_launch(void* const* d_in, const int* in_sizes, int n_in,
                              void* d_out, int out_size) {
    // metadata order: x, neigh_effect, neigh_transform, n_param, ew, eb, tw, tb
    const float* ne = (const float*)d_in[1];
    const float* nt = (const float*)d_in[2];
    const float* np = (const float*)d_in[3];
    const float* ew = (const float*)d_in[4];
    const float* eb = (const float*)d_in[5];
    const float* tw = (const float*)d_in[6];
    const float* tb = (const float*)d_in[7];
    float* out = (float*)d_out;

    fused_all<<<128 * GROUPS, 256>>>(ne, nt, np, ew, eb, tw, tb, out);
}

// round 5
// speedup vs baseline: 1.2261x; 1.0449x over previous
#include <cuda_runtime.h>
#include <math.h>

#define K  32
#define B  16384
#define DA 128
#define SPLITS 16   // CTAs per residue; CTA = (residue, split), 8 warps = 8 b-rows

// Fine-grained fused kernel (round-3 grid: 2048 CTAs self-balance across SMs)
// with prefetch-before-softmax so HBM streams from cycle 0.
//
// Reshape-trick index: x_sum[b,d] = sum_k nt[k,b,d] * w[k, (b&127)*128 + d];
// all b with residue r = b&127 share one 128-column softmax (smem, per CTA).
//
// nt (256 MB, single-use, 2x L2) -> __ldcs evict-first; outputs -> __stcs.
// Softmax is two-pass (running max, reload ne from L2 for exp) to keep the
// 8 prefetched float4s resident without spilling.

__global__ void __launch_bounds__(256) fused_all(
    const float* __restrict__ ne,   // [K, B]
    const float* __restrict__ nt,   // [K, B, DA]
    const float* __restrict__ np,   // [DA]
    const float* __restrict__ ew,   // [DA]
    const float* __restrict__ eb,   // [1]
    const float* __restrict__ tw,   // [DA]
    const float* __restrict__ tb,   // [DA]
    float* __restrict__ out)        // [B + B*DA]
{
    const int r = blockIdx.x & 127;      // residue
    const int s = blockIdx.x >> 7;       // split in [0, SPLITS)
    const int t = threadIdx.x;
    const int warp = t >> 5;
    const int lane = t & 31;
    const int b = r + 128 * (s * 8 + warp);

    __shared__ float wsm[K][DA];         // 16 KB softmax weights for this residue

    const size_t kstride4 = (size_t)B * DA / 4;   // float4 stride between k-slices
    const float4* nt4 = reinterpret_cast<const float4*>(nt + (size_t)b * DA) + lane;
    const float4* w4  = reinterpret_cast<const float4*>(&wsm[0][0]) + lane;  // + k*32

    // ---- prefetch batch 0 (k = 0..7) BEFORE softmax: HBM busy immediately ----
    float4 a[8];
#pragma unroll
    for (int j = 0; j < 8; j++)
        a[j] = __ldcs(nt4 + (size_t)j * kstride4);

    // ---- two-pass softmax: threads 0..127 each own one column (reg-lean) ----
    if (t < DA) {
        const float* nec = ne + r * DA + t;
        float m = -1e30f;
#pragma unroll
        for (int k = 0; k < K; k++)
            m = fmaxf(m, __ldg(nec + k * B));
        float ssum = 0.0f;
#pragma unroll
        for (int k = 0; k < K; k++) {
            const float e = __expf(__ldg(nec + k * B) - m);   // L2 hit on reload
            wsm[k][t] = e;
            ssum += e;
        }
        const float inv = __frcp_rn(ssum);
#pragma unroll
        for (int k = 0; k < K; k++)
            wsm[k][t] *= inv;
    }
    __syncthreads();

    // ---- streaming accumulation: batch 0 from prefetch, then k0 = 8,16,24 ----
    float4 acc = make_float4(0.f, 0.f, 0.f, 0.f);

#pragma unroll
    for (int j = 0; j < 8; j++) {
        const float4 w = w4[j * 32];                 // conflict-free LDS.128
        acc.x = fmaf(a[j].x, w.x, acc.x);
        acc.y = fmaf(a[j].y, w.y, acc.y);
        acc.z = fmaf(a[j].z, w.z, acc.z);
        acc.w = fmaf(a[j].w, w.w, acc.w);
    }

#pragma unroll
    for (int k0 = 8; k0 < K; k0 += 8) {
#pragma unroll
        for (int j = 0; j < 8; j++)
            a[j] = __ldcs(nt4 + (size_t)(k0 + j) * kstride4);
#pragma unroll
        for (int j = 0; j < 8; j++) {
            const float4 w = w4[(k0 + j) * 32];
            acc.x = fmaf(a[j].x, w.x, acc.x);
            acc.y = fmaf(a[j].y, w.y, acc.y);
            acc.z = fmaf(a[j].z, w.z, acc.z);
            acc.w = fmaf(a[j].w, w.w, acc.w);
        }
    }

    // ---- epilogue ----
    const float4 npv = __ldg(reinterpret_cast<const float4*>(np) + lane);
    float4 x_;
    x_.x = npv.x * acc.x;
    x_.y = npv.y * acc.y;
    x_.z = npv.z * acc.z;
    x_.w = npv.w * acc.w;

    const float4 ewv = __ldg(reinterpret_cast<const float4*>(ew) + lane);
    float dot = x_.x * ewv.x + x_.y * ewv.y + x_.z * ewv.z + x_.w * ewv.w;
#pragma unroll
    for (int off = 16; off > 0; off >>= 1)
        dot += __shfl_xor_sync(0xFFFFFFFFu, dot, off);

    const float effect = __frcp_rn(1.0f + __expf(-(dot + __ldg(eb))));

    if (lane == 0) __stcs(out + b, effect);

    const float4 twv = __ldg(reinterpret_cast<const float4*>(tw) + lane);
    const float4 tbv = __ldg(reinterpret_cast<const float4*>(tb) + lane);
    float4 res;
    res.x = effect * fmaf(twv.x, x_.x, tbv.x);
    res.y = effect * fmaf(twv.y, x_.y, tbv.y);
    res.z = effect * fmaf(twv.z, x_.z, tbv.z);
    res.w = effect * fmaf(twv.w, x_.w, tbv.w);

    __stcs(reinterpret_cast<float4*>(out + B + (size_t)b * DA) + lane, res);
}

extern "C" void kernel_launch(void* const* d_in, const int* in_sizes, int n_in,
                              void* d_out, int out_size) {
    // metadata order: x, neigh_effect, neigh_transform, n_param, ew, eb, tw, tb
    const float* ne = (const float*)d_in[1];
    const float* nt = (const float*)d_in[2];
    const float* np = (const float*)d_in[3];
    const float* ew = (const float*)d_in[4];
    const float* eb = (const float*)d_in[5];
    const float* tw = (const float*)d_in[6];
    const float* tb = (const float*)d_in[7];
    float* out = (float*)d_out;

    // 128 residues x 16 splits = 2048 CTAs; 8 warps/CTA -> one b-row per warp
    fused_all<<<128 * SPLITS, 256>>>(ne, nt, np, ew, eb, tw, tb, out);
}